// round 15
// baseline (speedup 1.0000x reference)
#include <cuda_runtime.h>
#include <cuda_fp16.h>
#include <math.h>

#define NN   50000
#define EE   1600000
#define BKT  128          // fixed bucket capacity per dst node (P(deg>128) ~ e^-60)

// ---- device scratch ----
__device__ uint4 g_hh4[NN * 8];      // h for layers 1/2 in fp16: 64 half = 128B/node
__device__ uint2 g_hh16[NN * 4];     // h for layer 3 in fp16: 16 half = 32B/node
__device__ float g_h2[NN * 64];      // aggregation output (fp32, next lin input)
__device__ float g_asrc[NN];
__device__ float g_adst[NN];
__device__ float g_amax[3];          // monotone (atomicMax only)
__device__ int   g_cnt[NN];          // degree; zeroed by agg16 (last reader) -> replay-safe
__device__ unsigned short g_srcs16[NN * BKT];   // bucketed src indices (12.8MB)

__device__ __forceinline__ void atomicMaxF(float* a, float v) {
    int old = __float_as_int(*a);
    while (__int_as_float(old) < v) {
        int assumed = old;
        old = atomicCAS((int*)a, assumed, __float_as_int(v));
        if (old == assumed) break;
    }
}

// ---- packed f32x2 helpers (sm_100a FFMA2) ----
__device__ __forceinline__ unsigned long long pack2(float v) {
    unsigned long long r;
    asm("mov.b64 %0, {%1, %1};" : "=l"(r) : "f"(v));
    return r;
}
__device__ __forceinline__ unsigned long long h2_to_f32x2(unsigned h2) {
    unsigned long long r;
    asm("{\n\t"
        ".reg .b16 lo, hi;\n\t"
        ".reg .f32 x, y;\n\t"
        "mov.b32 {lo, hi}, %1;\n\t"
        "cvt.f32.f16 x, lo;\n\t"
        "cvt.f32.f16 y, hi;\n\t"
        "mov.b64 %0, {x, y};\n\t"
        "}" : "=l"(r) : "r"(h2));
    return r;
}
__device__ __forceinline__ void ffma2(unsigned long long& acc, unsigned long long a,
                                      unsigned long long b) {
    asm("fma.rn.f32x2 %0, %1, %2, %0;" : "+l"(acc) : "l"(a), "l"(b));
}
__device__ __forceinline__ float2 unpack2(unsigned long long v) {
    float2 f;
    asm("mov.b64 {%0, %1}, %2;" : "=f"(f.x), "=f"(f.y) : "l"(v));
    return f;
}

// ================= bucket build: hist + scatter fused =================
__global__ void build_kernel(const int* __restrict__ ei) {
    int i = blockIdx.x * blockDim.x + threadIdx.x;
    if (i < EE / 4) {
        int4 s4 = reinterpret_cast<const int4*>(ei)[i];
        int4 d4 = reinterpret_cast<const int4*>(ei + EE)[i];
        int r0 = atomicAdd(&g_cnt[d4.x], 1);
        int r1 = atomicAdd(&g_cnt[d4.y], 1);
        int r2 = atomicAdd(&g_cnt[d4.z], 1);
        int r3 = atomicAdd(&g_cnt[d4.w], 1);
        if (r0 < BKT) g_srcs16[d4.x * BKT + r0] = (unsigned short)s4.x;
        if (r1 < BKT) g_srcs16[d4.y * BKT + r1] = (unsigned short)s4.y;
        if (r2 < BKT) g_srcs16[d4.z * BKT + r2] = (unsigned short)s4.z;
        if (r3 < BKT) g_srcs16[d4.w * BKT + r3] = (unsigned short)s4.w;
    }
}

// ================= linear: H(fp16) = X @ W + alphas + amax =================
// W streamed via __ldg (L1-resident); smem holds only the X tile -> high occupancy.
__device__ __forceinline__ float compo(float4 v, int u) {
    return u == 0 ? v.x : u == 1 ? v.y : u == 2 ? v.z : v.w;
}

// XSEL: 0 = param X, 1 = g_h2.  Output fp16: OUT=64 -> g_hh4, OUT=16 -> g_hh16.
template<int IN, int OUT, int NPT, int XSEL, int LAYER>
__global__ void __launch_bounds__(256, 6) lin_kernel(const float* __restrict__ Xp,
                                                     const float* __restrict__ W,
                                                     const float* __restrict__ av,
                                                     const float* __restrict__ adv)
{
    constexpr int TPG    = OUT / 4;
    constexpr int GROUPS = 256 / TPG;
    constexpr int NPB    = GROUPS * NPT;
    __shared__ float4 sx4[NPB * IN / 4];

    const float* X = (XSEL == 0) ? Xp : g_h2;
    const float4* X4 = reinterpret_cast<const float4*>(X);
    const float4* W4 = reinterpret_cast<const float4*>(W);

    int tid = threadIdx.x;
    int node0 = blockIdx.x * NPB;

    for (int i = tid; i < NPB * IN / 4; i += 256) {
        int n = node0 + i / (IN / 4);
        sx4[i] = (n < NN) ? X4[(size_t)n * (IN / 4) + (i % (IN / 4))]
                          : make_float4(0.f, 0.f, 0.f, 0.f);
    }
    __syncthreads();

    int grp = tid / TPG;
    int c4  = (tid % TPG) * 4;
    int c4g = c4 >> 2;

    float acc[NPT][4];
#pragma unroll
    for (int n = 0; n < NPT; n++)
#pragma unroll
        for (int c = 0; c < 4; c++) acc[n][c] = 0.f;

#pragma unroll 8
    for (int k4 = 0; k4 < IN / 4; k4++) {
        float4 xv[NPT];
#pragma unroll
        for (int n = 0; n < NPT; n++)
            xv[n] = sx4[(grp * NPT + n) * (IN / 4) + k4];
#pragma unroll
        for (int u = 0; u < 4; u++) {
            float4 wv = __ldg(&W4[(k4 * 4 + u) * (OUT / 4) + c4g]);
#pragma unroll
            for (int n = 0; n < NPT; n++) {
                float xk = compo(xv[n], u);
                acc[n][0] = fmaf(xk, wv.x, acc[n][0]);
                acc[n][1] = fmaf(xk, wv.y, acc[n][1]);
                acc[n][2] = fmaf(xk, wv.z, acc[n][2]);
                acc[n][3] = fmaf(xk, wv.w, acc[n][3]);
            }
        }
    }

    float4 avv  = *reinterpret_cast<const float4*>(&av[c4]);
    float4 advv = *reinterpret_cast<const float4*>(&adv[c4]);

    __half* Hh = (OUT == 64) ? reinterpret_cast<__half*>(g_hh4)
                             : reinterpret_cast<__half*>(g_hh16);

    float local_mx = -1e30f;
#pragma unroll
    for (int n = 0; n < NPT; n++) {
        int node = node0 + grp * NPT + n;
        if (node < NN) {
            __half2 ha = __floats2half2_rn(acc[n][0], acc[n][1]);
            __half2 hb = __floats2half2_rn(acc[n][2], acc[n][3]);
            __half2* dst = reinterpret_cast<__half2*>(Hh + (size_t)node * OUT + c4);
            dst[0] = ha; dst[1] = hb;
        }

        float vs = acc[n][0] * avv.x + acc[n][1] * avv.y + acc[n][2] * avv.z + acc[n][3] * avv.w;
        float vd = acc[n][0] * advv.x + acc[n][1] * advv.y + acc[n][2] * advv.z + acc[n][3] * advv.w;
#pragma unroll
        for (int off = TPG / 2; off >= 1; off >>= 1) {
            vs += __shfl_xor_sync(0xffffffffu, vs, off);
            vd += __shfl_xor_sync(0xffffffffu, vd, off);
        }
        if ((tid % TPG) == 0 && node < NN) {
            g_asrc[node] = vs;
            g_adst[node] = vd;
            local_mx = fmaxf(local_mx, vs);
        }
    }
#pragma unroll
    for (int off = 16; off >= 1; off >>= 1)
        local_mx = fmaxf(local_mx, __shfl_xor_sync(0xffffffffu, local_mx, off));
    if ((tid & 31) == 0) atomicMaxF(&g_amax[LAYER], local_mx);
}

// ================= single-pass aggregation, C=64 fp16, packed FFMA2 =================
template<bool RELU, int LAYER>
__global__ void __launch_bounds__(256) agg64_kernel(const float* __restrict__ b)
{
    __shared__ float2 stage[8][32];
    int w = (blockIdx.x * blockDim.x + threadIdx.x) >> 5;
    int lane = threadIdx.x & 31;
    int wwarp = threadIdx.x >> 5;
    if (w >= NN) return;

    int start = w * BKT;
    int deg = g_cnt[w]; if (deg > BKT) deg = BKT;
    int end = start + deg;
    float adst = g_adst[w];
    float C = fmaxf(adst + g_amax[LAYER], 0.f);

    int grp = lane >> 3;
    int q   = lane & 7;
    unsigned long long a01 = 0, a23 = 0, a45 = 0, a67 = 0;
    float psum = 0.f;

    for (int j0 = start; j0 < end; j0 += 32) {
        int j = j0 + lane;
        float p = 0.f; int s = 0;
        if (j < end) {
            s = (int)g_srcs16[j];
            float t = g_asrc[s] + adst;
            float e = (t > 0.f) ? t : 0.2f * t;
            p = __expf(e - C);
            psum += p;
        }
        stage[wwarp][lane] = make_float2(p, __int_as_float(s));
        __syncwarp();
        int cnt = end - j0;

        if (cnt >= 32) {
            float2 ps[8];
#pragma unroll
            for (int e = 0; e < 8; e++)
                ps[e] = stage[wwarp][(e >> 1) * 8 + (e & 1) * 4 + grp];
            uint4 hv[8];
#pragma unroll
            for (int e = 0; e < 8; e++)
                hv[e] = g_hh4[(size_t)__float_as_int(ps[e].y) * 8 + q];
#pragma unroll
            for (int e = 0; e < 8; e++) {
                unsigned long long pk2 = pack2(ps[e].x);
                ffma2(a01, pk2, h2_to_f32x2(hv[e].x));
                ffma2(a23, pk2, h2_to_f32x2(hv[e].y));
                ffma2(a45, pk2, h2_to_f32x2(hv[e].z));
                ffma2(a67, pk2, h2_to_f32x2(hv[e].w));
            }
        } else {
#pragma unroll
            for (int kb = 0; kb < 32; kb += 8) {
                if (kb < cnt) {
                    float2 psA = stage[wwarp][kb + grp];
                    float2 psB = stage[wwarp][kb + 4 + grp];
                    uint4 ha = g_hh4[(size_t)__float_as_int(psA.y) * 8 + q];
                    uint4 hb = g_hh4[(size_t)__float_as_int(psB.y) * 8 + q];
                    unsigned long long pkA = pack2(psA.x);
                    unsigned long long pkB = pack2(psB.x);
                    ffma2(a01, pkA, h2_to_f32x2(ha.x));
                    ffma2(a23, pkA, h2_to_f32x2(ha.y));
                    ffma2(a45, pkA, h2_to_f32x2(ha.z));
                    ffma2(a67, pkA, h2_to_f32x2(ha.w));
                    ffma2(a01, pkB, h2_to_f32x2(hb.x));
                    ffma2(a23, pkB, h2_to_f32x2(hb.y));
                    ffma2(a45, pkB, h2_to_f32x2(hb.z));
                    ffma2(a67, pkB, h2_to_f32x2(hb.w));
                }
            }
        }
        __syncwarp();
    }
#pragma unroll
    for (int o = 16; o; o >>= 1) psum += __shfl_xor_sync(0xffffffffu, psum, o);

    float2 u01 = unpack2(a01), u23 = unpack2(a23), u45 = unpack2(a45), u67 = unpack2(a67);
    float acc[8] = {u01.x, u01.y, u23.x, u23.y, u45.x, u45.y, u67.x, u67.y};
#pragma unroll
    for (int o = 8; o <= 16; o <<= 1)
#pragma unroll
        for (int u = 0; u < 8; u++)
            acc[u] += __shfl_xor_sync(0xffffffffu, acc[u], o);

    if (lane < 8) {
        float inv = 1.f / (psum + 1e-16f);
        int ch8 = q * 8;
        float4 b0 = *reinterpret_cast<const float4*>(&b[ch8]);
        float4 b1 = *reinterpret_cast<const float4*>(&b[ch8 + 4]);
        float v0 = acc[0] * inv + b0.x, v1 = acc[1] * inv + b0.y;
        float v2 = acc[2] * inv + b0.z, v3 = acc[3] * inv + b0.w;
        float v4 = acc[4] * inv + b1.x, v5 = acc[5] * inv + b1.y;
        float v6 = acc[6] * inv + b1.z, v7 = acc[7] * inv + b1.w;
        if (RELU) {
            v0 = fmaxf(v0, 0.f); v1 = fmaxf(v1, 0.f); v2 = fmaxf(v2, 0.f); v3 = fmaxf(v3, 0.f);
            v4 = fmaxf(v4, 0.f); v5 = fmaxf(v5, 0.f); v6 = fmaxf(v6, 0.f); v7 = fmaxf(v7, 0.f);
        }
        *reinterpret_cast<float4*>(&g_h2[(size_t)w * 64 + ch8])     = make_float4(v0, v1, v2, v3);
        *reinterpret_cast<float4*>(&g_h2[(size_t)w * 64 + ch8 + 4]) = make_float4(v4, v5, v6, v7);
    }
}

// ================= single-pass aggregation, C=16 fp16; zeroes g_cnt =================
__global__ void __launch_bounds__(256) agg16_kernel(const float* __restrict__ b,
                                                    float* __restrict__ O)
{
    __shared__ float2 stage[8][32];
    int w = (blockIdx.x * blockDim.x + threadIdx.x) >> 5;
    int lane = threadIdx.x & 31;
    int wwarp = threadIdx.x >> 5;
    if (w >= NN) return;

    int start = w * BKT;
    int deg = g_cnt[w]; if (deg > BKT) deg = BKT;
    int end = start + deg;
    float adst = g_adst[w];
    float C = fmaxf(adst + g_amax[2], 0.f);

    int grp = lane >> 2;
    int qv  = lane & 3;
    float psum = 0.f;
    unsigned long long a01 = 0, a23 = 0;

    for (int j0 = start; j0 < end; j0 += 32) {
        int j = j0 + lane;
        float p = 0.f; int s = 0;
        if (j < end) {
            s = (int)g_srcs16[j];
            float t = g_asrc[s] + adst;
            float e = (t > 0.f) ? t : 0.2f * t;
            p = __expf(e - C);
            psum += p;
        }
        stage[wwarp][lane] = make_float2(p, __int_as_float(s));
        __syncwarp();
        int cnt = end - j0;

        if (cnt >= 32) {
            float2 ps[4];
#pragma unroll
            for (int c = 0; c < 4; c++) ps[c] = stage[wwarp][c * 8 + grp];
            uint2 hv[4];
#pragma unroll
            for (int c = 0; c < 4; c++)
                hv[c] = g_hh16[(size_t)__float_as_int(ps[c].y) * 4 + qv];
#pragma unroll
            for (int c = 0; c < 4; c++) {
                unsigned long long pk2 = pack2(ps[c].x);
                ffma2(a01, pk2, h2_to_f32x2(hv[c].x));
                ffma2(a23, pk2, h2_to_f32x2(hv[c].y));
            }
        } else {
#pragma unroll
            for (int kb = 0; kb < 32; kb += 8) {
                if (kb < cnt) {
                    float2 ps = stage[wwarp][kb + grp];
                    uint2 hv = g_hh16[(size_t)__float_as_int(ps.y) * 4 + qv];
                    unsigned long long pk2 = pack2(ps.x);
                    ffma2(a01, pk2, h2_to_f32x2(hv.x));
                    ffma2(a23, pk2, h2_to_f32x2(hv.y));
                }
            }
        }
        __syncwarp();
    }
#pragma unroll
    for (int o = 16; o; o >>= 1) psum += __shfl_xor_sync(0xffffffffu, psum, o);

    float2 u01 = unpack2(a01), u23 = unpack2(a23);
    float ac0 = u01.x, ac1 = u01.y, ac2 = u23.x, ac3 = u23.y;
#pragma unroll
    for (int o = 4; o <= 16; o <<= 1) {
        ac0 += __shfl_xor_sync(0xffffffffu, ac0, o);
        ac1 += __shfl_xor_sync(0xffffffffu, ac1, o);
        ac2 += __shfl_xor_sync(0xffffffffu, ac2, o);
        ac3 += __shfl_xor_sync(0xffffffffu, ac3, o);
    }

    if (lane < 4) {
        float inv = 1.f / (psum + 1e-16f);
        int ch4 = qv * 4;
        float4 bb = *reinterpret_cast<const float4*>(&b[ch4]);
        *reinterpret_cast<float4*>(&O[(size_t)w * 16 + ch4]) =
            make_float4(ac0 * inv + bb.x, ac1 * inv + bb.y,
                        ac2 * inv + bb.z, ac3 * inv + bb.w);
    }
    if (lane == 0) g_cnt[w] = 0;   // restore for next graph replay
}

// ================= launch =================
static cudaStream_t g_s2 = 0;
static cudaEvent_t  g_eF = 0, g_eJ = 0;

extern "C" void kernel_launch(void* const* d_in, const int* in_sizes, int n_in,
                              void* d_out, int out_size) {
    const float* x   = (const float*)d_in[0];
    const int*   ei  = (const int*)  d_in[1];
    const float* W1  = (const float*)d_in[3];
    const float* as1 = (const float*)d_in[4];
    const float* ad1 = (const float*)d_in[5];
    const float* b1  = (const float*)d_in[6];
    const float* W2  = (const float*)d_in[7];
    const float* as2 = (const float*)d_in[8];
    const float* ad2 = (const float*)d_in[9];
    const float* b2  = (const float*)d_in[10];
    const float* W3  = (const float*)d_in[11];
    const float* as3 = (const float*)d_in[12];
    const float* ad3 = (const float*)d_in[13];
    const float* b3  = (const float*)d_in[14];
    float* out = (float*)d_out;

    if (!g_s2) {
        cudaStreamCreateWithFlags(&g_s2, cudaStreamNonBlocking);
        cudaEventCreateWithFlags(&g_eF, cudaEventDisableTiming);
        cudaEventCreateWithFlags(&g_eJ, cudaEventDisableTiming);
    }

    // ---- fork: lin1 on side stream, bucket build on main stream ----
    cudaEventRecord(g_eF, 0);
    cudaStreamWaitEvent(g_s2, g_eF, 0);
    lin_kernel<128, 64, 2, 0, 0><<<(NN + 31) / 32, 256, 0, g_s2>>>(x, W1, as1, ad1);
    cudaEventRecord(g_eJ, g_s2);

    build_kernel<<<(EE / 4 + 255) / 256, 256>>>(ei);

    cudaStreamWaitEvent(0, g_eJ, 0);   // join lin1 into main stream

    const int AGG_GRID = (NN + 7) / 8;

    agg64_kernel<true, 0><<<AGG_GRID, 256>>>(b1);

    lin_kernel<64, 64, 2, 1, 1><<<(NN + 31) / 32, 256>>>(x, W2, as2, ad2);
    agg64_kernel<true, 1><<<AGG_GRID, 256>>>(b2);

    lin_kernel<64, 16, 1, 1, 2><<<(NN + 63) / 64, 256>>>(x, W3, as3, ad3);
    agg16_kernel<<<AGG_GRID, 256>>>(b3, out);
}

// round 16
// speedup vs baseline: 1.0417x; 1.0417x over previous
#include <cuda_runtime.h>
#include <cuda_fp16.h>
#include <math.h>

#define NN   50000
#define EE   1600000
#define BKT  128          // fixed bucket capacity per dst node (P(deg>128) ~ e^-60)

// ---- device scratch ----
__device__ uint4 g_hh4[NN * 8];      // lin1/lin2 output in fp16: 64 half = 128B/node
__device__ uint4 g_hh2[NN * 8];      // agg64 output in fp16 (lin2/lin3 input)
__device__ uint2 g_hh16[NN * 4];     // lin3 output in fp16: 16 half = 32B/node
__device__ float g_asrc[NN];
__device__ float g_adst[NN];
__device__ float g_amax[3];          // monotone (atomicMax only)
__device__ int   g_cnt[NN];          // degree; zeroed by agg16 (last reader) -> replay-safe
__device__ unsigned short g_srcs16[NN * BKT];   // bucketed src indices (12.8MB)

__device__ __forceinline__ void atomicMaxF(float* a, float v) {
    int old = __float_as_int(*a);
    while (__int_as_float(old) < v) {
        int assumed = old;
        old = atomicCAS((int*)a, assumed, __float_as_int(v));
        if (old == assumed) break;
    }
}

// ---- packed f32x2 helpers (sm_100a FFMA2) ----
__device__ __forceinline__ unsigned long long pack2(float v) {
    unsigned long long r;
    asm("mov.b64 %0, {%1, %1};" : "=l"(r) : "f"(v));
    return r;
}
__device__ __forceinline__ unsigned long long h2_to_f32x2(unsigned h2) {
    unsigned long long r;
    asm("{\n\t"
        ".reg .b16 lo, hi;\n\t"
        ".reg .f32 x, y;\n\t"
        "mov.b32 {lo, hi}, %1;\n\t"
        "cvt.f32.f16 x, lo;\n\t"
        "cvt.f32.f16 y, hi;\n\t"
        "mov.b64 %0, {x, y};\n\t"
        "}" : "=l"(r) : "r"(h2));
    return r;
}
__device__ __forceinline__ void ffma2(unsigned long long& acc, unsigned long long a,
                                      unsigned long long b) {
    asm("fma.rn.f32x2 %0, %1, %2, %0;" : "+l"(acc) : "l"(a), "l"(b));
}
__device__ __forceinline__ float2 unpack2(unsigned long long v) {
    float2 f;
    asm("mov.b64 {%0, %1}, %2;" : "=f"(f.x), "=f"(f.y) : "l"(v));
    return f;
}

// ================= bucket build: hist + scatter fused =================
__global__ void build_kernel(const int* __restrict__ ei) {
    int i = blockIdx.x * blockDim.x + threadIdx.x;
    if (i < EE / 4) {
        int4 s4 = reinterpret_cast<const int4*>(ei)[i];
        int4 d4 = reinterpret_cast<const int4*>(ei + EE)[i];
        int r0 = atomicAdd(&g_cnt[d4.x], 1);
        int r1 = atomicAdd(&g_cnt[d4.y], 1);
        int r2 = atomicAdd(&g_cnt[d4.z], 1);
        int r3 = atomicAdd(&g_cnt[d4.w], 1);
        if (r0 < BKT) g_srcs16[d4.x * BKT + r0] = (unsigned short)s4.x;
        if (r1 < BKT) g_srcs16[d4.y * BKT + r1] = (unsigned short)s4.y;
        if (r2 < BKT) g_srcs16[d4.z * BKT + r2] = (unsigned short)s4.z;
        if (r3 < BKT) g_srcs16[d4.w * BKT + r3] = (unsigned short)s4.w;
    }
}

// ================= linear: H(fp16) = X @ W + alphas + amax =================
// R14 structure: W staged in smem, NPT nodes/thread. XHALF: input from fp16 g_hh2.
__device__ __forceinline__ float compo(float4 v, int u) {
    return u == 0 ? v.x : u == 1 ? v.y : u == 2 ? v.z : v.w;
}

// XHALF: 0 = fp32 param X, 1 = fp16 g_hh2.  Output: OUT=64 -> g_hh4, OUT=16 -> g_hh16.
template<int IN, int OUT, int NPT, int XHALF, int LAYER>
__global__ void __launch_bounds__(256, 5) lin_kernel(const float* __restrict__ Xp,
                                                     const float* __restrict__ W,
                                                     const float* __restrict__ av,
                                                     const float* __restrict__ adv)
{
    constexpr int TPG    = OUT / 4;
    constexpr int GROUPS = 256 / TPG;
    constexpr int NPB    = GROUPS * NPT;
    __shared__ float4 sw4[IN * OUT / 4];
    __shared__ float4 sx4[NPB * IN / 4];

    const float4* X4 = reinterpret_cast<const float4*>(Xp);
    const float4* W4 = reinterpret_cast<const float4*>(W);

    int tid = threadIdx.x;
    int node0 = blockIdx.x * NPB;

    for (int i = tid; i < IN * OUT / 4; i += 256) sw4[i] = W4[i];
    if (XHALF == 0) {
        for (int i = tid; i < NPB * IN / 4; i += 256) {
            int n = node0 + i / (IN / 4);
            sx4[i] = (n < NN) ? X4[(size_t)n * (IN / 4) + (i % (IN / 4))]
                              : make_float4(0.f, 0.f, 0.f, 0.f);
        }
    } else {
        for (int i = tid; i < NPB * IN / 8; i += 256) {
            int nl = i / (IN / 8);
            int q  = i % (IN / 8);
            int n  = node0 + nl;
            uint4 hv = (n < NN) ? g_hh2[(size_t)n * (IN / 8) + q]
                                : make_uint4(0u, 0u, 0u, 0u);
            float2 f0 = __half22float2(*reinterpret_cast<__half2*>(&hv.x));
            float2 f1 = __half22float2(*reinterpret_cast<__half2*>(&hv.y));
            float2 f2 = __half22float2(*reinterpret_cast<__half2*>(&hv.z));
            float2 f3 = __half22float2(*reinterpret_cast<__half2*>(&hv.w));
            sx4[nl * (IN / 4) + 2 * q]     = make_float4(f0.x, f0.y, f1.x, f1.y);
            sx4[nl * (IN / 4) + 2 * q + 1] = make_float4(f2.x, f2.y, f3.x, f3.y);
        }
    }
    __syncthreads();

    int grp = tid / TPG;
    int c4  = (tid % TPG) * 4;

    float acc[NPT][4];
#pragma unroll
    for (int n = 0; n < NPT; n++)
#pragma unroll
        for (int c = 0; c < 4; c++) acc[n][c] = 0.f;

#pragma unroll 4
    for (int k4 = 0; k4 < IN / 4; k4++) {
        float4 xv[NPT];
#pragma unroll
        for (int n = 0; n < NPT; n++)
            xv[n] = sx4[(grp * NPT + n) * (IN / 4) + k4];
#pragma unroll
        for (int u = 0; u < 4; u++) {
            float4 wv = sw4[(k4 * 4 + u) * (OUT / 4) + (c4 >> 2)];
#pragma unroll
            for (int n = 0; n < NPT; n++) {
                float xk = compo(xv[n], u);
                acc[n][0] = fmaf(xk, wv.x, acc[n][0]);
                acc[n][1] = fmaf(xk, wv.y, acc[n][1]);
                acc[n][2] = fmaf(xk, wv.z, acc[n][2]);
                acc[n][3] = fmaf(xk, wv.w, acc[n][3]);
            }
        }
    }

    float4 avv  = *reinterpret_cast<const float4*>(&av[c4]);
    float4 advv = *reinterpret_cast<const float4*>(&adv[c4]);

    __half* Hh = (OUT == 64) ? reinterpret_cast<__half*>(g_hh4)
                             : reinterpret_cast<__half*>(g_hh16);

    float local_mx = -1e30f;
#pragma unroll
    for (int n = 0; n < NPT; n++) {
        int node = node0 + grp * NPT + n;
        if (node < NN) {
            __half2 ha = __floats2half2_rn(acc[n][0], acc[n][1]);
            __half2 hb = __floats2half2_rn(acc[n][2], acc[n][3]);
            __half2* dst = reinterpret_cast<__half2*>(Hh + (size_t)node * OUT + c4);
            dst[0] = ha; dst[1] = hb;
        }

        float vs = acc[n][0] * avv.x + acc[n][1] * avv.y + acc[n][2] * avv.z + acc[n][3] * avv.w;
        float vd = acc[n][0] * advv.x + acc[n][1] * advv.y + acc[n][2] * advv.z + acc[n][3] * advv.w;
#pragma unroll
        for (int off = TPG / 2; off >= 1; off >>= 1) {
            vs += __shfl_xor_sync(0xffffffffu, vs, off);
            vd += __shfl_xor_sync(0xffffffffu, vd, off);
        }
        if ((tid % TPG) == 0 && node < NN) {
            g_asrc[node] = vs;
            g_adst[node] = vd;
            local_mx = fmaxf(local_mx, vs);
        }
    }
#pragma unroll
    for (int off = 16; off >= 1; off >>= 1)
        local_mx = fmaxf(local_mx, __shfl_xor_sync(0xffffffffu, local_mx, off));
    if ((tid & 31) == 0) atomicMaxF(&g_amax[LAYER], local_mx);
}

// ================= single-pass aggregation, C=64 fp16 in/out, packed FFMA2 =============
template<bool RELU, int LAYER>
__global__ void __launch_bounds__(256) agg64_kernel(const float* __restrict__ b)
{
    __shared__ float2 stage[8][32];
    int w = (blockIdx.x * blockDim.x + threadIdx.x) >> 5;
    int lane = threadIdx.x & 31;
    int wwarp = threadIdx.x >> 5;
    if (w >= NN) return;

    int start = w * BKT;
    int deg = g_cnt[w]; if (deg > BKT) deg = BKT;
    int end = start + deg;
    float adst = g_adst[w];
    float C = fmaxf(adst + g_amax[LAYER], 0.f);

    int grp = lane >> 3;
    int q   = lane & 7;
    unsigned long long a01 = 0, a23 = 0, a45 = 0, a67 = 0;
    float psum = 0.f;

    for (int j0 = start; j0 < end; j0 += 32) {
        int j = j0 + lane;
        float p = 0.f; int s = 0;
        if (j < end) {
            s = (int)g_srcs16[j];
            float t = g_asrc[s] + adst;
            float e = (t > 0.f) ? t : 0.2f * t;
            p = __expf(e - C);
            psum += p;
        }
        stage[wwarp][lane] = make_float2(p, __int_as_float(s));
        __syncwarp();
        int cnt = end - j0;

        if (cnt >= 32) {
            float2 ps[8];
#pragma unroll
            for (int e = 0; e < 8; e++)
                ps[e] = stage[wwarp][(e >> 1) * 8 + (e & 1) * 4 + grp];
            uint4 hv[8];
#pragma unroll
            for (int e = 0; e < 8; e++)
                hv[e] = g_hh4[(size_t)__float_as_int(ps[e].y) * 8 + q];
#pragma unroll
            for (int e = 0; e < 8; e++) {
                unsigned long long pk2 = pack2(ps[e].x);
                ffma2(a01, pk2, h2_to_f32x2(hv[e].x));
                ffma2(a23, pk2, h2_to_f32x2(hv[e].y));
                ffma2(a45, pk2, h2_to_f32x2(hv[e].z));
                ffma2(a67, pk2, h2_to_f32x2(hv[e].w));
            }
        } else {
#pragma unroll
            for (int kb = 0; kb < 32; kb += 8) {
                if (kb < cnt) {
                    float2 psA = stage[wwarp][kb + grp];
                    float2 psB = stage[wwarp][kb + 4 + grp];
                    uint4 ha = g_hh4[(size_t)__float_as_int(psA.y) * 8 + q];
                    uint4 hb = g_hh4[(size_t)__float_as_int(psB.y) * 8 + q];
                    unsigned long long pkA = pack2(psA.x);
                    unsigned long long pkB = pack2(psB.x);
                    ffma2(a01, pkA, h2_to_f32x2(ha.x));
                    ffma2(a23, pkA, h2_to_f32x2(ha.y));
                    ffma2(a45, pkA, h2_to_f32x2(ha.z));
                    ffma2(a67, pkA, h2_to_f32x2(ha.w));
                    ffma2(a01, pkB, h2_to_f32x2(hb.x));
                    ffma2(a23, pkB, h2_to_f32x2(hb.y));
                    ffma2(a45, pkB, h2_to_f32x2(hb.z));
                    ffma2(a67, pkB, h2_to_f32x2(hb.w));
                }
            }
        }
        __syncwarp();
    }
#pragma unroll
    for (int o = 16; o; o >>= 1) psum += __shfl_xor_sync(0xffffffffu, psum, o);

    float2 u01 = unpack2(a01), u23 = unpack2(a23), u45 = unpack2(a45), u67 = unpack2(a67);
    float acc[8] = {u01.x, u01.y, u23.x, u23.y, u45.x, u45.y, u67.x, u67.y};
#pragma unroll
    for (int o = 8; o <= 16; o <<= 1)
#pragma unroll
        for (int u = 0; u < 8; u++)
            acc[u] += __shfl_xor_sync(0xffffffffu, acc[u], o);

    if (lane < 8) {
        float inv = 1.f / (psum + 1e-16f);
        int ch8 = q * 8;
        float4 b0 = *reinterpret_cast<const float4*>(&b[ch8]);
        float4 b1 = *reinterpret_cast<const float4*>(&b[ch8 + 4]);
        float v0 = acc[0] * inv + b0.x, v1 = acc[1] * inv + b0.y;
        float v2 = acc[2] * inv + b0.z, v3 = acc[3] * inv + b0.w;
        float v4 = acc[4] * inv + b1.x, v5 = acc[5] * inv + b1.y;
        float v6 = acc[6] * inv + b1.z, v7 = acc[7] * inv + b1.w;
        if (RELU) {
            v0 = fmaxf(v0, 0.f); v1 = fmaxf(v1, 0.f); v2 = fmaxf(v2, 0.f); v3 = fmaxf(v3, 0.f);
            v4 = fmaxf(v4, 0.f); v5 = fmaxf(v5, 0.f); v6 = fmaxf(v6, 0.f); v7 = fmaxf(v7, 0.f);
        }
        __half2 h0 = __floats2half2_rn(v0, v1);
        __half2 h1 = __floats2half2_rn(v2, v3);
        __half2 h2v = __floats2half2_rn(v4, v5);
        __half2 h3 = __floats2half2_rn(v6, v7);
        g_hh2[(size_t)w * 8 + q] = make_uint4(
            *reinterpret_cast<unsigned*>(&h0), *reinterpret_cast<unsigned*>(&h1),
            *reinterpret_cast<unsigned*>(&h2v), *reinterpret_cast<unsigned*>(&h3));
    }
}

// ================= single-pass aggregation, C=16 fp16; zeroes g_cnt =================
__global__ void __launch_bounds__(256) agg16_kernel(const float* __restrict__ b,
                                                    float* __restrict__ O)
{
    __shared__ float2 stage[8][32];
    int w = (blockIdx.x * blockDim.x + threadIdx.x) >> 5;
    int lane = threadIdx.x & 31;
    int wwarp = threadIdx.x >> 5;
    if (w >= NN) return;

    int start = w * BKT;
    int deg = g_cnt[w]; if (deg > BKT) deg = BKT;
    int end = start + deg;
    float adst = g_adst[w];
    float C = fmaxf(adst + g_amax[2], 0.f);

    int grp = lane >> 2;
    int qv  = lane & 3;
    float psum = 0.f;
    unsigned long long a01 = 0, a23 = 0;

    for (int j0 = start; j0 < end; j0 += 32) {
        int j = j0 + lane;
        float p = 0.f; int s = 0;
        if (j < end) {
            s = (int)g_srcs16[j];
            float t = g_asrc[s] + adst;
            float e = (t > 0.f) ? t : 0.2f * t;
            p = __expf(e - C);
            psum += p;
        }
        stage[wwarp][lane] = make_float2(p, __int_as_float(s));
        __syncwarp();
        int cnt = end - j0;

        if (cnt >= 32) {
            float2 ps[4];
#pragma unroll
            for (int c = 0; c < 4; c++) ps[c] = stage[wwarp][c * 8 + grp];
            uint2 hv[4];
#pragma unroll
            for (int c = 0; c < 4; c++)
                hv[c] = g_hh16[(size_t)__float_as_int(ps[c].y) * 4 + qv];
#pragma unroll
            for (int c = 0; c < 4; c++) {
                unsigned long long pk2 = pack2(ps[c].x);
                ffma2(a01, pk2, h2_to_f32x2(hv[c].x));
                ffma2(a23, pk2, h2_to_f32x2(hv[c].y));
            }
        } else {
#pragma unroll
            for (int kb = 0; kb < 32; kb += 8) {
                if (kb < cnt) {
                    float2 ps = stage[wwarp][kb + grp];
                    uint2 hv = g_hh16[(size_t)__float_as_int(ps.y) * 4 + qv];
                    unsigned long long pk2 = pack2(ps.x);
                    ffma2(a01, pk2, h2_to_f32x2(hv.x));
                    ffma2(a23, pk2, h2_to_f32x2(hv.y));
                }
            }
        }
        __syncwarp();
    }
#pragma unroll
    for (int o = 16; o; o >>= 1) psum += __shfl_xor_sync(0xffffffffu, psum, o);

    float2 u01 = unpack2(a01), u23 = unpack2(a23);
    float ac0 = u01.x, ac1 = u01.y, ac2 = u23.x, ac3 = u23.y;
#pragma unroll
    for (int o = 4; o <= 16; o <<= 1) {
        ac0 += __shfl_xor_sync(0xffffffffu, ac0, o);
        ac1 += __shfl_xor_sync(0xffffffffu, ac1, o);
        ac2 += __shfl_xor_sync(0xffffffffu, ac2, o);
        ac3 += __shfl_xor_sync(0xffffffffu, ac3, o);
    }

    if (lane < 4) {
        float inv = 1.f / (psum + 1e-16f);
        int ch4 = qv * 4;
        float4 bb = *reinterpret_cast<const float4*>(&b[ch4]);
        *reinterpret_cast<float4*>(&O[(size_t)w * 16 + ch4]) =
            make_float4(ac0 * inv + bb.x, ac1 * inv + bb.y,
                        ac2 * inv + bb.z, ac3 * inv + bb.w);
    }
    if (lane == 0) g_cnt[w] = 0;   // restore for next graph replay
}

// ================= launch =================
static cudaStream_t g_s2 = 0;
static cudaEvent_t  g_eF = 0, g_eJ = 0;

extern "C" void kernel_launch(void* const* d_in, const int* in_sizes, int n_in,
                              void* d_out, int out_size) {
    const float* x   = (const float*)d_in[0];
    const int*   ei  = (const int*)  d_in[1];
    const float* W1  = (const float*)d_in[3];
    const float* as1 = (const float*)d_in[4];
    const float* ad1 = (const float*)d_in[5];
    const float* b1  = (const float*)d_in[6];
    const float* W2  = (const float*)d_in[7];
    const float* as2 = (const float*)d_in[8];
    const float* ad2 = (const float*)d_in[9];
    const float* b2  = (const float*)d_in[10];
    const float* W3  = (const float*)d_in[11];
    const float* as3 = (const float*)d_in[12];
    const float* ad3 = (const float*)d_in[13];
    const float* b3  = (const float*)d_in[14];
    float* out = (float*)d_out;

    if (!g_s2) {
        cudaStreamCreateWithFlags(&g_s2, cudaStreamNonBlocking);
        cudaEventCreateWithFlags(&g_eF, cudaEventDisableTiming);
        cudaEventCreateWithFlags(&g_eJ, cudaEventDisableTiming);
    }

    // ---- fork: lin1 on side stream, bucket build on main stream ----
    cudaEventRecord(g_eF, 0);
    cudaStreamWaitEvent(g_s2, g_eF, 0);
    lin_kernel<128, 64, 2, 0, 0><<<(NN + 31) / 32, 256, 0, g_s2>>>(x, W1, as1, ad1);
    cudaEventRecord(g_eJ, g_s2);

    build_kernel<<<(EE / 4 + 255) / 256, 256>>>(ei);

    cudaStreamWaitEvent(0, g_eJ, 0);   // join lin1 into main stream

    const int AGG_GRID = (NN + 7) / 8;

    agg64_kernel<true, 0><<<AGG_GRID, 256>>>(b1);

    lin_kernel<64, 64, 4, 1, 1><<<(NN + 63) / 64, 256>>>(x, W2, as2, ad2);
    agg64_kernel<true, 1><<<AGG_GRID, 256>>>(b2);

    lin_kernel<64, 16, 2, 1, 2><<<(NN + 127) / 128, 256>>>(x, W3, as3, ad3);
    agg16_kernel<<<AGG_GRID, 256>>>(b3, out);
}